// round 15
// baseline (speedup 1.0000x reference)
#include <cuda_runtime.h>
#include <cuda_fp16.h>
#include <cstdint>

// Problem constants: B=4, S=2048, D=512, H=8, HD=64

// fp16 copies of the three inputs (hi conversion), flat [B*S, D]
__device__ __align__(256) __half g_In[3 * 4 * 2048 * 512];
// attention output, fp16 (hi), flat [B*S, D]
__device__ __align__(256) __half g_Oh[4 * 2048 * 512];
// Transposed+split weights: [mat][n][k] fp16, K-major
__device__ __align__(256) __half g_Wt_hi[4 * 512 * 512];
__device__ __align__(256) __half g_Wt_lo[4 * 512 * 512];
// Q (hi only, pre-scaled by 0.125) + split K/V in head layout [B*H][S][64]
__device__ __align__(256) __half g_Qh[4*8*2048*64];
__device__ __align__(256) __half g_Kh[4*8*2048*64], g_Kl[4*8*2048*64];
__device__ __align__(256) __half g_Vh[4*8*2048*64], g_Vl[4*8*2048*64];

// ---------------------------------------------------------------------------
__device__ __forceinline__ uint32_t smem_u32(const void* p) {
    uint32_t a;
    asm("{ .reg .u64 t; cvta.to.shared.u64 t, %1; cvt.u32.u64 %0, t; }"
        : "=r"(a) : "l"(p));
    return a;
}
#define CP_ASYNC16(dst, src) \
    asm volatile("cp.async.cg.shared.global [%0], [%1], 16;" :: "r"(dst), "l"(src))
#define CP_COMMIT() asm volatile("cp.async.commit_group;" ::: "memory")
#define CP_WAIT0()  asm volatile("cp.async.wait_group 0;" ::: "memory")
#define CP_WAIT1()  asm volatile("cp.async.wait_group 1;" ::: "memory")

#define LDSM_X4(r0,r1,r2,r3,addr) \
    asm volatile("ldmatrix.sync.aligned.m8n8.x4.shared.b16 {%0,%1,%2,%3}, [%4];" \
        : "=r"(r0),"=r"(r1),"=r"(r2),"=r"(r3) : "r"(addr))
#define LDSM_X4T(r0,r1,r2,r3,addr) \
    asm volatile("ldmatrix.sync.aligned.m8n8.x4.trans.shared.b16 {%0,%1,%2,%3}, [%4];" \
        : "=r"(r0),"=r"(r1),"=r"(r2),"=r"(r3) : "r"(addr))

__device__ __forceinline__ void mma4(float* d, const uint32_t* a, uint32_t b0, uint32_t b1) {
    asm volatile(
        "mma.sync.aligned.m16n8k16.row.col.f32.f16.f16.f32 "
        "{%0,%1,%2,%3}, {%4,%5,%6,%7}, {%8,%9}, {%0,%1,%2,%3};"
        : "+f"(d[0]), "+f"(d[1]), "+f"(d[2]), "+f"(d[3])
        : "r"(a[0]), "r"(a[1]), "r"(a[2]), "r"(a[3]), "r"(b0), "r"(b1));
}

// pack {lo, hi} floats into f16x2 (lo value in low half)
__device__ __forceinline__ uint32_t packhf(float lo, float hi) {
    uint32_t r;
    asm("cvt.rn.f16x2.f32 %0, %1, %2;" : "=r"(r) : "f"(hi), "f"(lo));
    return r;
}
// residual (lo part of hi/lo split) given already-packed hi pair
__device__ __forceinline__ uint32_t respackh(uint32_t hpk, float lo, float hi) {
    __half2 h = *reinterpret_cast<__half2*>(&hpk);
    return packhf(lo - __low2float(h), hi - __high2float(h));
}
__device__ __forceinline__ uint32_t swz(uint32_t off) {
    return off ^ ((off >> 3) & 0x70u);
}

// ---------------------------------------------------------------------------
// Input conversion: queries/keys/values fp32 -> fp16 (hi), flat layout.
// Each thread converts 8 elements.
// ---------------------------------------------------------------------------
__global__ __launch_bounds__(256) void conv_in_kernel(
    const float* __restrict__ Q, const float* __restrict__ K,
    const float* __restrict__ V)
{
    const int z = blockIdx.y;
    const float* src = (z == 0) ? Q : (z == 1) ? K : V;
    __half* dst = g_In + (size_t)z * 4194304;
    size_t i0 = ((size_t)blockIdx.x * 256 + threadIdx.x) * 8;
    float4 a = *(const float4*)&src[i0];
    float4 b = *(const float4*)&src[i0 + 4];
    uint4 o;
    o.x = packhf(a.x, a.y); o.y = packhf(a.z, a.w);
    o.z = packhf(b.x, b.y); o.w = packhf(b.z, b.w);
    *(uint4*)&dst[i0] = o;
}

// ---------------------------------------------------------------------------
// Weight prep: W[k][n] fp32 -> Wt[n][k] fp16 hi/lo (K-major), all 4 matrices.
// ---------------------------------------------------------------------------
__global__ __launch_bounds__(256) void prep_w_kernel(
    const float* __restrict__ Wq, const float* __restrict__ Wk,
    const float* __restrict__ Wv, const float* __restrict__ Wo)
{
    const int z = blockIdx.z;
    const float* W = (z == 0) ? Wq : (z == 1) ? Wk : (z == 2) ? Wv : Wo;
    __shared__ float t[32][33];
    const int tx = threadIdx.x, ty = threadIdx.y;
    const int n = blockIdx.x * 32 + tx;
    const int k0 = blockIdx.y * 32;
#pragma unroll
    for (int i = 0; i < 4; i++)
        t[ty + i * 8][tx] = W[(size_t)(k0 + ty + i * 8) * 512 + n];
    __syncthreads();
#pragma unroll
    for (int i = 0; i < 4; i++) {
        int nn = blockIdx.x * 32 + ty + i * 8;
        int kk = k0 + tx;
        float v = t[tx][ty + i * 8];
        __half hh = __float2half(v);
        __half ll = __float2half(v - __half2float(hh));
        g_Wt_hi[(size_t)z * 262144 + (size_t)nn * 512 + kk] = hh;
        g_Wt_lo[(size_t)z * 262144 + (size_t)nn * 512 + kk] = ll;
    }
}

// ---------------------------------------------------------------------------
// mma.sync GEMM: fully cp.async (A fp16 from g_In/g_Oh, B fp16 weights),
// double buffered, 2 CTAs/SM. 2-term split: Ah*(Bh+Bl).
// MODE 0: z-indexed QKV projections (Q -> hi only; K/V -> hi+lo),
//         K/V CTAs fully past valid_len exit early.
// MODE 1: out = g_Oh @ Wo + bo (fp32 flat).
// smem: A0 18432 | A1 18432 | B0 [hi|lo] 36864 | B1 36864 = 110592
// ---------------------------------------------------------------------------
#define ABUF   18432
#define BBASE  36864
#define BBUF   36864
#define BOFF_L 18432
#define SMEM_GEMM 110592

template<int MODE>
__global__ __launch_bounds__(256, 2) void gemm_mma_kernel(
    const float* __restrict__ bq, const float* __restrict__ bk,
    const float* __restrict__ bv,
    const int* __restrict__ vlens, float* __restrict__ dst_ext)
{
    extern __shared__ char smc[];
    const uint32_t sb = smem_u32(smc);
    const int tid = threadIdx.x;
    const int wid = tid >> 5, lane = tid & 31;
    const int g = lane >> 2, t4 = lane & 3;
    const int wm = (wid >> 2) * 64;
    const int wn = (wid & 3) * 32;
    const int row0 = blockIdx.y * 128;
    const int col0 = blockIdx.x * 128;
    const int mat = (MODE == 0) ? (int)blockIdx.z : 3;

    if (MODE == 0 && mat >= 1) {
        int vl = vlens[row0 >> 11];
        int ve = (vl == 0) ? 2048 : vl;
        if ((row0 & 2047) >= ve) return;
    }

    const __half* A = (MODE == 0) ? (g_In + (size_t)mat * 4194304) : g_Oh;
    const float* bias = (MODE == 0) ? ((mat == 0) ? bq : (mat == 1) ? bk : bv) : bq;
    const __half* Bhg = g_Wt_hi + (size_t)mat * 262144;
    const __half* Blg = g_Wt_lo + (size_t)mat * 262144;

    float acc[4][4][4];
#pragma unroll
    for (int i = 0; i < 4; i++)
#pragma unroll
        for (int j = 0; j < 4; j++)
#pragma unroll
            for (int k = 0; k < 4; k++) acc[i][j][k] = 0.f;

    // One commit group per chunk: A (4 cp.async/thread) + B (8 cp.async/thread)
    auto load = [&](int c) {
        const int kc0 = c * 64;
        const uint32_t ab = sb + (uint32_t)(c & 1) * ABUF;
#pragma unroll
        for (int it = 0; it < 4; it++) {
            int idx = it * 256 + tid;
            int r = idx >> 3, gr = idx & 7;
            CP_ASYNC16(ab + (uint32_t)(r * 144 + gr * 16),
                       &A[(size_t)(row0 + r) * 512 + kc0 + gr * 8]);
        }
        const uint32_t bb = sb + BBASE + (uint32_t)(c & 1) * BBUF;
#pragma unroll
        for (int it = 0; it < 4; it++) {
            int idx = it * 256 + tid;
            int n = idx >> 3, gr = idx & 7;
            uint32_t off = (uint32_t)(n * 144 + gr * 16);
            CP_ASYNC16(bb + off,          &Bhg[(size_t)(col0 + n) * 512 + kc0 + gr * 8]);
            CP_ASYNC16(bb + BOFF_L + off, &Blg[(size_t)(col0 + n) * 512 + kc0 + gr * 8]);
        }
        CP_COMMIT();
    };

    load(0);

    const int lrow = lane & 15;
    const int lcolb = (lane >> 4) * 16;

    for (int c = 0; c < 8; c++) {
        if (c < 7) { load(c + 1); CP_WAIT1(); }
        else       { CP_WAIT0(); }
        __syncthreads();

        const uint32_t abase = sb + (uint32_t)(c & 1) * ABUF;
        const uint32_t bbase = sb + BBASE + (uint32_t)(c & 1) * BBUF;
#pragma unroll
        for (int ks = 0; ks < 4; ks++) {
            const uint32_t colb = (uint32_t)(ks * 32 + lcolb);
            uint32_t ah[4][4], bfh[2][4], bfl[2][4];
#pragma unroll
            for (int mt = 0; mt < 4; mt++) {
                uint32_t ra = abase + (uint32_t)(wm + mt * 16 + lrow) * 144 + colb;
                LDSM_X4(ah[mt][0], ah[mt][1], ah[mt][2], ah[mt][3], ra);
            }
#pragma unroll
            for (int p = 0; p < 2; p++) {
                uint32_t rb = bbase + (uint32_t)(wn + p * 16 + lrow) * 144 + colb;
                LDSM_X4(bfh[p][0], bfh[p][1], bfh[p][2], bfh[p][3], rb);
                LDSM_X4(bfl[p][0], bfl[p][1], bfl[p][2], bfl[p][3], rb + BOFF_L);
            }
#pragma unroll
            for (int mt = 0; mt < 4; mt++)
#pragma unroll
                for (int nt = 0; nt < 4; nt++) {
                    int p = nt >> 1, q = nt & 1;
                    mma4(acc[mt][nt], ah[mt], bfh[p][q], bfh[p][q + 2]);
                    mma4(acc[mt][nt], ah[mt], bfl[p][q], bfl[p][q + 2]);
                }
        }
        __syncthreads();
    }

    float* T = (float*)smc;
#pragma unroll
    for (int mt = 0; mt < 4; mt++)
#pragma unroll
        for (int nt = 0; nt < 4; nt++) {
            int row = wm + mt * 16 + g;
            int col = wn + nt * 8 + 2 * t4;
            *(float2*)&T[row * 132 + col] = make_float2(acc[mt][nt][0], acc[mt][nt][1]);
            *(float2*)&T[(row + 8) * 132 + col] = make_float2(acc[mt][nt][2], acc[mt][nt][3]);
        }
    __syncthreads();

#pragma unroll
    for (int it = 0; it < 16; it++) {
        int idx = it * 256 + tid;
        int row = idx >> 5, cg = (idx & 31) * 4;
        float4 v = *(float4*)&T[row * 132 + cg];
        float4 bvv = *(const float4*)&bias[col0 + cg];
        v.x += bvv.x; v.y += bvv.y; v.z += bvv.z; v.w += bvv.w;
        if (MODE == 0) {
            if (mat == 0) { v.x *= 0.125f; v.y *= 0.125f; v.z *= 0.125f; v.w *= 0.125f; }
            uint32_t h0 = packhf(v.x, v.y), h1 = packhf(v.z, v.w);
            int cc = col0 + cg, hh = cc >> 6, hd = cc & 63;
            int rr = row0 + row, bb2 = rr >> 11, s = rr & 2047;
            size_t base2 = (((size_t)(bb2 * 8 + hh)) * 2048 + s) * 64 + hd;
            if (mat == 0) {
                *(uint2*)&g_Qh[base2] = make_uint2(h0, h1);
            } else {
                uint32_t l0 = respackh(h0, v.x, v.y), l1 = respackh(h1, v.z, v.w);
                __half* Dh = (mat == 1) ? g_Kh : g_Vh;
                __half* Dl = (mat == 1) ? g_Kl : g_Vl;
                *(uint2*)&Dh[base2] = make_uint2(h0, h1);
                *(uint2*)&Dl[base2] = make_uint2(l0, l1);
            }
        } else {
            *(float4*)&dst_ext[(size_t)(row0 + row) * 512 + col0 + cg] = v;
        }
    }
}

// ---------------------------------------------------------------------------
// FA2-style mma.sync attention, fp16.
// QK^T: 2-term (Qh*Kh + Qh*Kl); P single fp16; PV: 2-term (P*Vh + P*Vl).
// Output written as fp16 (hi) to g_Oh — identical value to the old
// fp32-store + hi-convert path. 80 KB smem, 2 CTAs/SM.
// ---------------------------------------------------------------------------
#define ATT_SMEM 81920

__global__ __launch_bounds__(256, 2) void attn_mma_kernel(const int* __restrict__ valid_lens)
{
    extern __shared__ char smc[];
    const uint32_t sb = smem_u32(smc);
    const int tid = threadIdx.x;
    const int wid = tid >> 5, lane = tid & 31;
    const int t4 = lane & 3, g = lane >> 2;
    const int bh = blockIdx.y, b = bh >> 3, h = bh & 7;
    const int q0 = blockIdx.x * 128;
    const int wq = wid * 16;

    const size_t hbase = (size_t)bh * (2048 * 64);
    const __half* Qhg = g_Qh + hbase;
    const __half* Khg = g_Kh + hbase;
    const __half* Klg = g_Kl + hbase;
    const __half* Vhg = g_Vh + hbase;
    const __half* Vlg = g_Vl + hbase;

    const int vlen = valid_lens[b];
    int ntiles = (vlen > 0) ? ((vlen + 63) >> 6) : 32;
    if (ntiles > 32) ntiles = 32;
    const float mskv = (vlen == 0) ? 0.f : -1e6f;

    // Q hi loads (rows q0..q0+127), swizzled
#pragma unroll
    for (int it = 0; it < 4; it++) {
        int idx = it * 256 + tid;
        int row = idx >> 3, c = idx & 7;
        uint32_t off = swz((uint32_t)(row * 128 + c * 16));
        CP_ASYNC16(sb + 65536 + off, &Qhg[(size_t)(q0 + row) * 64 + c * 8]);
    }
    auto load_kv = [&](int t) {
        const uint32_t kb = sb + (t & 1) * 32768;
        const int ks0 = t << 6;
#pragma unroll
        for (int it = 0; it < 2; it++) {
            int idx = it * 256 + tid;
            int row = idx >> 3, c = idx & 7;
            uint32_t off = swz((uint32_t)(row * 128 + c * 16));
            size_t go = (size_t)(ks0 + row) * 64 + c * 8;
            CP_ASYNC16(kb + off,         &Khg[go]);
            CP_ASYNC16(kb + 8192 + off,  &Klg[go]);
            CP_ASYNC16(kb + 16384 + off, &Vhg[go]);
            CP_ASYNC16(kb + 24576 + off, &Vlg[go]);
        }
        CP_COMMIT();
    };
    load_kv(0);

    uint32_t qh[4][4];
    float o[8][4];
#pragma unroll
    for (int i = 0; i < 8; i++)
#pragma unroll
        for (int j = 0; j < 4; j++) o[i][j] = 0.f;
    float l0 = 0.f, l1 = 0.f;

    const int qrow = wq + (lane & 15);
    const int qcolb = (lane >> 4) * 16;
    const int krow_r = ((lane >> 4) & 1) * 8 + (lane & 7);
    const int kcol_half = ((lane >> 3) & 1) * 16;

    for (int t = 0; t < ntiles; t++) {
        CP_WAIT0();
        __syncthreads();
        if (t == 0) {
#pragma unroll
            for (int kst = 0; kst < 4; kst++) {
                uint32_t a1 = sb + 65536 + swz((uint32_t)(qrow * 128 + kst * 32 + qcolb));
                LDSM_X4(qh[kst][0], qh[kst][1], qh[kst][2], qh[kst][3], a1);
            }
        }
        if (t + 1 < ntiles) load_kv(t + 1);

        const uint32_t kb = sb + (t & 1) * 32768;
        float s[8][4];
#pragma unroll
        for (int i = 0; i < 8; i++)
#pragma unroll
            for (int j = 0; j < 4; j++) s[i][j] = 0.f;

        // S = Q @ K^T (2-term: Qh*Kh + Qh*Kl)
#pragma unroll
        for (int kst = 0; kst < 4; kst++) {
#pragma unroll
            for (int np = 0; np < 4; np++) {
                uint32_t addr = kb + swz((uint32_t)((np * 16 + krow_r) * 128 + kst * 32 + kcol_half));
                uint32_t r0, r1, r2, r3, u0, u1, u2, u3;
                LDSM_X4(r0, r1, r2, r3, addr);
                LDSM_X4(u0, u1, u2, u3, addr + 8192);
                mma4(s[2 * np],     qh[kst], r0, r1);
                mma4(s[2 * np],     qh[kst], u0, u1);
                mma4(s[2 * np + 1], qh[kst], r2, r3);
                mma4(s[2 * np + 1], qh[kst], u2, u3);
            }
        }

        // mask + exp + row-sum (no max subtraction; scores pre-scaled by 1/8)
        const int ks0 = t << 6;
#pragma unroll
        for (int nt = 0; nt < 8; nt++) {
            int cb = ks0 + nt * 8 + 2 * t4;
            float x0 = (cb < vlen)     ? s[nt][0] : mskv;
            float x1 = (cb + 1 < vlen) ? s[nt][1] : mskv;
            float x2 = (cb < vlen)     ? s[nt][2] : mskv;
            float x3 = (cb + 1 < vlen) ? s[nt][3] : mskv;
            float p0 = __expf(x0), p1 = __expf(x1), p2 = __expf(x2), p3 = __expf(x3);
            l0 += p0 + p1;
            l1 += p2 + p3;
            s[nt][0] = p0; s[nt][1] = p1; s[nt][2] = p2; s[nt][3] = p3;
        }
        // pack P as single fp16 A-fragments
        uint32_t pa[4][4];
#pragma unroll
        for (int kst = 0; kst < 4; kst++) {
            int n0 = 2 * kst, n1 = n0 + 1;
            pa[kst][0] = packhf(s[n0][0], s[n0][1]);
            pa[kst][1] = packhf(s[n0][2], s[n0][3]);
            pa[kst][2] = packhf(s[n1][0], s[n1][1]);
            pa[kst][3] = packhf(s[n1][2], s[n1][3]);
        }

        // O += P @ V (2-term: P*Vh + P*Vl)
#pragma unroll
        for (int kst = 0; kst < 4; kst++) {
#pragma unroll
            for (int np = 0; np < 4; np++) {
                uint32_t addr = kb + 16384 +
                    swz((uint32_t)((kst * 16 + krow_r) * 128 + np * 32 + kcol_half));
                uint32_t v0, v1, v2, v3, w0, w1, w2, w3;
                LDSM_X4T(v0, v1, v2, v3, addr);
                LDSM_X4T(w0, w1, w2, w3, addr + 8192);
                mma4(o[2 * np],     pa[kst], v0, v2);
                mma4(o[2 * np],     pa[kst], w0, w2);
                mma4(o[2 * np + 1], pa[kst], v1, v3);
                mma4(o[2 * np + 1], pa[kst], w1, w3);
            }
        }
    }

    l0 += __shfl_xor_sync(0xffffffffu, l0, 1);
    l0 += __shfl_xor_sync(0xffffffffu, l0, 2);
    l1 += __shfl_xor_sync(0xffffffffu, l1, 1);
    l1 += __shfl_xor_sync(0xffffffffu, l1, 2);
    float inv0 = 1.f / l0, inv1 = 1.f / l1;
    int r0 = q0 + wq + g, r1 = r0 + 8;
    __half* O0 = &g_Oh[((size_t)b * 2048 + r0) * 512 + h * 64];
    __half* O1 = &g_Oh[((size_t)b * 2048 + r1) * 512 + h * 64];
#pragma unroll
    for (int nt = 0; nt < 8; nt++) {
        *(uint32_t*)&O0[nt * 8 + 2 * t4] = packhf(o[nt][0] * inv0, o[nt][1] * inv0);
        *(uint32_t*)&O1[nt * 8 + 2 * t4] = packhf(o[nt][2] * inv1, o[nt][3] * inv1);
    }
}

// ---------------------------------------------------------------------------
extern "C" void kernel_launch(void* const* d_in, const int* in_sizes, int n_in,
                              void* d_out, int out_size)
{
    const float* queries = (const float*)d_in[0];
    const float* keys    = (const float*)d_in[1];
    const float* values  = (const float*)d_in[2];
    const int*   vlens   = (const int*)d_in[3];
    const float* Wq = (const float*)d_in[4];
    const float* bq = (const float*)d_in[5];
    const float* Wk = (const float*)d_in[6];
    const float* bk = (const float*)d_in[7];
    const float* Wv = (const float*)d_in[8];
    const float* bv = (const float*)d_in[9];
    const float* Wo = (const float*)d_in[10];
    const float* bo = (const float*)d_in[11];
    float* out = (float*)d_out;

    cudaFuncSetAttribute(gemm_mma_kernel<0>,
                         cudaFuncAttributeMaxDynamicSharedMemorySize, SMEM_GEMM);
    cudaFuncSetAttribute(gemm_mma_kernel<1>,
                         cudaFuncAttributeMaxDynamicSharedMemorySize, SMEM_GEMM);
    cudaFuncSetAttribute(attn_mma_kernel,
                         cudaFuncAttributeMaxDynamicSharedMemorySize, ATT_SMEM);

    // fp32 -> fp16 input conversion + weight prep (independent kernels)
    conv_in_kernel<<<dim3(2048, 3), 256>>>(queries, keys, values);
    prep_w_kernel<<<dim3(16, 16, 4), dim3(32, 8)>>>(Wq, Wk, Wv, Wo);

    gemm_mma_kernel<0><<<dim3(4, 64, 3), 256, SMEM_GEMM>>>(
        bq, bk, bv, vlens, nullptr);

    attn_mma_kernel<<<dim3(16, 32), 256, ATT_SMEM>>>(vlens);

    gemm_mma_kernel<1><<<dim3(4, 64), 256, SMEM_GEMM>>>(
        bq, nullptr, nullptr, vlens, out);
}